// round 16
// baseline (speedup 1.0000x reference)
#include <cuda_runtime.h>

#define BB 4
#define RR 64
#define FF 1024
#define DD 128
#define FT 32          // k2 f-tile width
#define NFT (FF/FT)    // 32 f-tiles

// ---------------- device scratch (static; no allocations) ----------------
__device__ float g_fproj[BB*FF*DD];
__device__ float g_rproj[BB*RR*DD];
__device__ float g_wd[DD];
__device__ float g_escore[BB*RR*FF];
__device__ float g_sums_part[NFT*BB*RR];
__device__ float g_msg_part[NFT*BB*RR*DD];

// ---------------- kernel 1: projections -----------------------------------
// 16-row x 64-col tiles, 256 threads, 1r x 4c per thread.
// Broadcast map: cg = t>>4 (warp-uniform cols -> W float4 broadcast, 2/warp),
//                r  = t&15 (per-lane rows    -> x scalar single-phase).
// blocks 0..511  : f_proj (rowtile = blk>>1 over 4096 rows, chalf = blk&1)
// blocks 512..543: r_proj + b1 (256 rows)
// block  544     : w_d column sums
#define K1_SMEM ((DD*64 + DD*18) * 4)

__global__ __launch_bounds__(256)
void k1_proj(const float* __restrict__ robot,
             const float* __restrict__ frontier,
             const float* __restrict__ W1,
             const float* __restrict__ b1) {
    extern __shared__ float sm[];
    float* w_s = sm;               // [k][c]  128 x 64 (column half)
    float* x_s = sm + DD*64;       // [k][r]  128 x 18 (16 rows + 2 pad)
    const int t   = threadIdx.x;
    const int blk = blockIdx.x;

    if (blk >= 544) {
        if (t < DD) {
            float s = 0.f;
            #pragma unroll 8
            for (int k = 0; k < DD; k++) s += W1[(2*DD + k)*DD + t];
            g_wd[t] = s;
        }
        return;
    }

    const float* Wbase;
    const float* X;
    float* O;
    int chalf;
    bool add_b1;
    if (blk < 512) {
        int rowtile = blk >> 1;  chalf = blk & 1;
        Wbase = W1 + DD*DD;                       // W1f
        X = frontier + (size_t)rowtile*16*DD;     // rows = (b,f) flattened
        O = g_fproj  + (size_t)rowtile*16*DD;
        add_b1 = false;
    } else {
        int idx = blk - 512;
        int rowtile = idx >> 1;  chalf = idx & 1;
        Wbase = W1;                               // W1r
        X = robot   + (size_t)rowtile*16*DD;      // rows = (b,r) flattened
        O = g_rproj + (size_t)rowtile*16*DD;
        add_b1 = true;
    }

    for (int i = t; i < DD*64; i += 256) {
        int k = i >> 6, c = i & 63;
        w_s[i] = Wbase[k*DD + chalf*64 + c];
    }
    for (int i = t; i < 16*DD; i += 256) {
        int r = i >> 7, k = i & 127;
        x_s[k*18 + r] = X[i];
    }
    __syncthreads();

    const int cg = t >> 4, r = t & 15;
    const int c0 = cg*4;
    float a0 = 0.f, a1 = 0.f, a2 = 0.f, a3 = 0.f;

    #pragma unroll 8
    for (int k = 0; k < DD; k++) {
        float  xv = x_s[k*18 + r];                    // 16 consecutive lanes: 1 phase
        float4 w4 = *(const float4*)&w_s[k*64 + c0];  // 2 distinct per warp: broadcast
        a0 = fmaf(xv, w4.x, a0);
        a1 = fmaf(xv, w4.y, a1);
        a2 = fmaf(xv, w4.z, a2);
        a3 = fmaf(xv, w4.w, a3);
    }

    if (add_b1) {
        const float* bp = b1 + chalf*64 + c0;
        a0 += bp[0]; a1 += bp[1]; a2 += bp[2]; a3 += bp[3];
    }

    *(float4*)&O[r*DD + chalf*64 + c0] = make_float4(a0, a1, a2, a3);
}

// ---------------- kernel 2: fused scores + exp + softmax partials + message partials
// grid 512: b = x>>7, ftile = (x>>2)&31, rq = x&3 (16 robots, 32 f per block)
// 256 threads, ~49KB smem -> 4 blocks/SM; grid 512 -> ~3.5 blocks/SM.
// Broadcast maps: phase A fx = t>>4 (fp2 broadcast), r = t&15;
//                 phase B dg = t>>4 (fr4 broadcast), r2 = t&15.
#define K2_SMEM_FLOATS (DD*17 + DD*34 + 16*33 + FT*132 + FT*17 + 2*DD + 16*16)
#define K2_SMEM (K2_SMEM_FLOATS * 4)

__global__ __launch_bounds__(256)
void k2_main(const float* __restrict__ frontier,
             const float* __restrict__ geo,
             const float* __restrict__ W2,
             const float* __restrict__ b2) {
    extern __shared__ float sm[];
    float*  rp_s  = sm;                      // [d][r]  128 x 17 (scalar reads)
    float*  fp_s  = rp_s  + DD*17;           // [d][f]  128 x 34 (even: aligned float2)
    float*  geo_s = fp_s  + DD*34;           // [r][f]   16 x 33
    float*  fr_s  = geo_s + 16*33;           // [f][d]   32 x 132
    float*  e_s   = fr_s  + FT*132;          // [f][r]   32 x 17
    float2* wz_s  = (float2*)(e_s + FT*17);  // 128 x {wd, w2}
    float*  ps_s  = e_s + FT*17 + 2*DD;      // 16 x 16

    const int t = threadIdx.x;
    const int x = blockIdx.x;
    const int b     = x >> 7;
    const int ftile = (x >> 2) & 31;
    const int rbase = (x & 3) * 16;
    const int fbase = ftile * FT;

    const float* RP = g_rproj + (size_t)(b*RR + rbase)*DD;
    for (int i = t; i < 16*DD; i += 256) { int r = i >> 7, d = i & 127; rp_s[d*17 + r] = RP[i]; }
    const float* FP = g_fproj + (size_t)(b*FF + fbase)*DD;
    for (int i = t; i < FT*DD; i += 256) { int f = i >> 7, d = i & 127; fp_s[d*34 + f] = FP[i]; }
    const float* FR = frontier + (size_t)(b*FF + fbase)*DD;
    for (int i = t; i < FT*DD; i += 256) { int f = i >> 7, d = i & 127; fr_s[f*132 + d] = FR[i]; }
    const float* G = geo + (size_t)(b*RR + rbase)*FF + fbase;
    for (int i = t; i < 16*FT; i += 256) { int r = i >> 5, f = i & 31; geo_s[r*33 + f] = G[r*FF + f]; }
    if (t < DD) wz_s[t] = make_float2(g_wd[t], W2[t]);
    __syncthreads();

    // ---- phase A: scores, 1r x 2f per thread over 16r x 32f ----
    const int fx = t >> 4, r = t & 15;
    const int f0 = fx*2;

    const float g0 = geo_s[r*33 + f0];
    const float g1 = geo_s[r*33 + f0 + 1];
    float a0 = 0.f, a1 = 0.f;

    #pragma unroll 8
    for (int d = 0; d < DD; d++) {
        float  rpv = rp_s[d*17 + r];                    // 16 consecutive lanes: 1 phase
        float2 fp2 = *(const float2*)&fp_s[d*34 + f0];  // 2 distinct per warp: broadcast
        float2 wz  = wz_s[d];                           // broadcast
        float v0 = rpv + fp2.x;
        float v1 = rpv + fp2.y;
        v0 = fmaf(g0, wz.x, v0);
        v1 = fmaf(g1, wz.x, v1);
        v0 = fmaxf(v0, 0.f);
        v1 = fmaxf(v1, 0.f);
        a0 = fmaf(v0, wz.y, a0);
        a1 = fmaf(v1, wz.y, a1);
    }

    const float b2v = b2[0];
    float e0 = __expf(fmaxf(a0 + b2v, 0.f));   // scores >= 0, small: exact softmax w/o max-sub
    float e1 = __expf(fmaxf(a1 + b2v, 0.f));
    e_s[(f0+0)*17 + r] = e0;
    e_s[(f0+1)*17 + r] = e1;
    ps_s[r*16 + fx] = e0 + e1;

    float* EO = g_escore + (size_t)(b*RR + rbase + r)*FF + fbase;
    *(float2*)&EO[f0] = make_float2(e0, e1);
    __syncthreads();

    if (t < 16) {
        float s = 0.f;
        #pragma unroll
        for (int q = 0; q < 16; q++) s += ps_s[t*16 + q];
        g_sums_part[ftile*(BB*RR) + b*RR + rbase + t] = s;
    }

    // ---- phase B: partial messages, 1r x 8d per thread over 16r x 128d ----
    const int dg = t >> 4, r2 = t & 15;
    const int d0 = dg*8;
    float m0=0.f,m1=0.f,m2=0.f,m3=0.f,m4=0.f,m5=0.f,m6=0.f,m7=0.f;

    #pragma unroll 4
    for (int f = 0; f < FT; f++) {
        float  ev = e_s[f*17 + r2];                        // 16 consecutive lanes
        float4 fA = *(const float4*)&fr_s[f*132 + d0];     // 2 distinct: broadcast
        float4 fB = *(const float4*)&fr_s[f*132 + d0 + 4];
        m0 = fmaf(ev, fA.x, m0);
        m1 = fmaf(ev, fA.y, m1);
        m2 = fmaf(ev, fA.z, m2);
        m3 = fmaf(ev, fA.w, m3);
        m4 = fmaf(ev, fB.x, m4);
        m5 = fmaf(ev, fB.y, m5);
        m6 = fmaf(ev, fB.z, m6);
        m7 = fmaf(ev, fB.w, m7);
    }

    float* MO = g_msg_part + (size_t)(ftile*(BB*RR) + b*RR + rbase + r2)*DD;
    *(float4*)&MO[d0]     = make_float4(m0, m1, m2, m3);
    *(float4*)&MO[d0 + 4] = make_float4(m4, m5, m6, m7);
}

// ---------------- kernel 3: normalize + outputs ----------------------------
// grid = 256 (one per (b,r)), 128 threads
__global__ __launch_bounds__(128)
void k3_out(const float* __restrict__ robot,
            const float* __restrict__ Wn,
            const float* __restrict__ bn,
            float* __restrict__ out) {
    __shared__ float comb[2*DD];
    const int br = blockIdx.x;
    const int t  = threadIdx.x;

    float s = 0.f;
    #pragma unroll 8
    for (int p = 0; p < NFT; p++) s += g_sums_part[p*(BB*RR) + br];
    const float inv = 1.0f / s;

    float mm = 0.f;
    #pragma unroll 8
    for (int p = 0; p < NFT; p++) mm += g_msg_part[(size_t)(p*(BB*RR) + br)*DD + t];
    comb[DD + t] = mm * inv;
    comb[t]      = robot[(size_t)br*DD + t];

    const float* E  = g_escore + (size_t)br*FF;
    float*       ew = out + (size_t)BB*RR*DD + (size_t)br*FF;
    #pragma unroll
    for (int k = 0; k < FF/DD; k++) ew[k*DD + t] = E[k*DD + t] * inv;
    __syncthreads();

    float acc = bn[t];
    #pragma unroll 8
    for (int k = 0; k < 2*DD; k++) acc = fmaf(comb[k], Wn[k*DD + t], acc);
    out[(size_t)br*DD + t] = fmaxf(acc, 0.f);
}

// ---------------- launch ----------------------------------------------------
extern "C" void kernel_launch(void* const* d_in, const int* in_sizes, int n_in,
                              void* d_out, int out_size) {
    const float* robot    = (const float*)d_in[0];
    const float* frontier = (const float*)d_in[1];
    const float* geo      = (const float*)d_in[2];
    const float* W1       = (const float*)d_in[3];
    const float* b1       = (const float*)d_in[4];
    const float* W2       = (const float*)d_in[5];
    const float* b2       = (const float*)d_in[6];
    const float* Wn       = (const float*)d_in[7];
    const float* bn       = (const float*)d_in[8];
    float* out = (float*)d_out;

    cudaFuncSetAttribute(k1_proj, cudaFuncAttributeMaxDynamicSharedMemorySize, K1_SMEM);
    cudaFuncSetAttribute(k2_main, cudaFuncAttributeMaxDynamicSharedMemorySize, K2_SMEM);

    k1_proj<<<545, 256, K1_SMEM>>>(robot, frontier, W1, b1);
    k2_main<<<512, 256, K2_SMEM>>>(frontier, geo, W2, b2);
    k3_out<<<256, 128>>>(robot, Wn, bn, out);
}

// round 17
// speedup vs baseline: 1.1701x; 1.1701x over previous
#include <cuda_runtime.h>

#define BB 4
#define RR 64
#define FF 1024
#define DD 128
#define FT 64          // k2 f-tile width
#define NFT (FF/FT)    // 16 f-tiles

typedef unsigned long long u64;

__device__ __forceinline__ u64 pk2(float a, float b) {
    u64 r; asm("mov.b64 %0, {%1, %2};" : "=l"(r) : "f"(a), "f"(b)); return r;
}
__device__ __forceinline__ void upk2(u64 v, float& a, float& b) {
    asm("mov.b64 {%0, %1}, %2;" : "=f"(a), "=f"(b) : "l"(v));
}
__device__ __forceinline__ u64 fma2v(u64 a, u64 b, u64 c) {
    u64 r; asm("fma.rn.f32x2 %0, %1, %2, %3;" : "=l"(r) : "l"(a), "l"(b), "l"(c)); return r;
}
__device__ __forceinline__ u64 add2v(u64 a, u64 b) {
    u64 r; asm("add.rn.f32x2 %0, %1, %2;" : "=l"(r) : "l"(a), "l"(b)); return r;
}
__device__ __forceinline__ u64 d2u_lo(double2 d) { return __double_as_longlong(d.x); }
__device__ __forceinline__ u64 d2u_hi(double2 d) { return __double_as_longlong(d.y); }

// ---------------- device scratch (static; no allocations) ----------------
__device__ float g_fproj[BB*FF*DD];
__device__ float g_rproj[BB*RR*DD];
__device__ float g_wd[DD];
__device__ float g_escore[BB*RR*FF];
__device__ float g_sums_part[NFT*BB*RR];
__device__ float g_msg_part[NFT*BB*RR*DD];

// ---------------- kernel 1: projections -----------------------------------
// 16-row x 64-col tiles, 256 threads, 1r x 4c per thread, f32x2 packed math.
// Broadcast map: cg = t>>4 (warp-uniform cols -> W LDS.128 broadcast),
//                r  = t&15 (per-lane rows    -> x scalar single-phase).
// blocks 0..511  : f_proj ; 512..543: r_proj + b1 ; 544: w_d
#define K1_SMEM ((DD*64 + DD*18) * 4)

__global__ __launch_bounds__(256)
void k1_proj(const float* __restrict__ robot,
             const float* __restrict__ frontier,
             const float* __restrict__ W1,
             const float* __restrict__ b1) {
    extern __shared__ float sm[];
    float* w_s = sm;               // [k][c]  128 x 64 (column half)
    float* x_s = sm + DD*64;       // [k][r]  128 x 18 (16 rows + 2 pad)
    const int t   = threadIdx.x;
    const int blk = blockIdx.x;

    if (blk >= 544) {
        if (t < DD) {
            float s = 0.f;
            #pragma unroll 8
            for (int k = 0; k < DD; k++) s += W1[(2*DD + k)*DD + t];
            g_wd[t] = s;
        }
        return;
    }

    const float* Wbase;
    const float* X;
    float* O;
    int chalf;
    bool add_b1;
    if (blk < 512) {
        int rowtile = blk >> 1;  chalf = blk & 1;
        Wbase = W1 + DD*DD;                       // W1f
        X = frontier + (size_t)rowtile*16*DD;
        O = g_fproj  + (size_t)rowtile*16*DD;
        add_b1 = false;
    } else {
        int idx = blk - 512;
        int rowtile = idx >> 1;  chalf = idx & 1;
        Wbase = W1;                               // W1r
        X = robot   + (size_t)rowtile*16*DD;
        O = g_rproj + (size_t)rowtile*16*DD;
        add_b1 = true;
    }

    for (int i = t; i < DD*64; i += 256) {
        int k = i >> 6, c = i & 63;
        w_s[i] = Wbase[k*DD + chalf*64 + c];
    }
    for (int i = t; i < 16*DD; i += 256) {
        int r = i >> 7, k = i & 127;
        x_s[k*18 + r] = X[i];
    }
    __syncthreads();

    const int cg = t >> 4, r = t & 15;
    const int c0 = cg*4;
    u64 a01 = 0, a23 = 0;   // packed {0.f,0.f} bit pattern == 0

    #pragma unroll 8
    for (int k = 0; k < DD; k++) {
        float xv = x_s[k*18 + r];                          // 1 phase
        u64 xx = pk2(xv, xv);
        double2 wp = *(const double2*)&w_s[k*64 + c0];     // LDS.128 broadcast
        a01 = fma2v(xx, d2u_lo(wp), a01);
        a23 = fma2v(xx, d2u_hi(wp), a23);
    }

    float o0, o1, o2, o3;
    upk2(a01, o0, o1);
    upk2(a23, o2, o3);
    if (add_b1) {
        const float* bp = b1 + chalf*64 + c0;
        o0 += bp[0]; o1 += bp[1]; o2 += bp[2]; o3 += bp[3];
    }
    *(float4*)&O[r*DD + chalf*64 + c0] = make_float4(o0, o1, o2, o3);
}

// ---------------- kernel 2: fused scores + exp + softmax partials + message partials
// grid 256: b = x>>6, ftile = (x>>2)&15, rq = x&3 (16 robots, 64 f per block)
// 256 threads, ~87KB smem -> 2 blocks/SM. f32x2 packed math in both phases.
// Broadcast maps: phase A fx = t>>4 (fp LDS.128 broadcast), r = t&15;
//                 phase B dg = t>>4 (fr LDS.128 broadcast), r2 = t&15.
#define K2_SMEM_FLOATS (DD*17 + DD*68 + 16*65 + FT*132 + FT*17 + 4*DD + 16*16)
#define K2_SMEM (K2_SMEM_FLOATS * 4)

__global__ __launch_bounds__(256)
void k2_main(const float* __restrict__ frontier,
             const float* __restrict__ geo,
             const float* __restrict__ W2,
             const float* __restrict__ b2) {
    extern __shared__ float sm[];
    float* rp_s  = sm;                 // [d][r]  128 x 17 (scalar)            base 0
    float* fp_s  = rp_s  + DD*17;      // [d][f]  128 x 68 (16B-aligned f4)    base 2176
    float* geo_s = fp_s  + DD*68;      // [r][f]   16 x 65                     base 10880
    float* fr_s  = geo_s + 16*65;      // [f][d]   64 x 132 (16B-aligned f4)   base 11920
    float* e_s   = fr_s  + FT*132;     // [f][r]   64 x 17                     base 20368
    float* wz_s  = e_s   + FT*17;      // [d][4] = {wd,wd,w2,w2}, LDS.128      base 21456
    float* ps_s  = wz_s  + 4*DD;       // 16 x 16                              base 21968

    const int t = threadIdx.x;
    const int x = blockIdx.x;
    const int b     = x >> 6;
    const int ftile = (x >> 2) & 15;
    const int rbase = (x & 3) * 16;
    const int fbase = ftile * FT;

    const float* RP = g_rproj + (size_t)(b*RR + rbase)*DD;
    for (int i = t; i < 16*DD; i += 256) { int r = i >> 7, d = i & 127; rp_s[d*17 + r] = RP[i]; }
    const float* FP = g_fproj + (size_t)(b*FF + fbase)*DD;
    for (int i = t; i < FT*DD; i += 256) { int f = i >> 7, d = i & 127; fp_s[d*68 + f] = FP[i]; }
    const float* FR = frontier + (size_t)(b*FF + fbase)*DD;
    for (int i = t; i < FT*DD; i += 256) { int f = i >> 7, d = i & 127; fr_s[f*132 + d] = FR[i]; }
    const float* G = geo + (size_t)(b*RR + rbase)*FF + fbase;
    for (int i = t; i < 16*FT; i += 256) { int r = i >> 6, f = i & 63; geo_s[r*65 + f] = G[r*FF + f]; }
    if (t < DD) {
        float wd = g_wd[t], w2v = W2[t];
        *(float4*)&wz_s[4*t] = make_float4(wd, wd, w2v, w2v);
    }
    __syncthreads();

    // ---- phase A: scores, 1r x 4f per thread over 16r x 64f, packed ----
    const int fx = t >> 4, r = t & 15;
    const int f0 = fx*4;

    const u64 g01 = pk2(geo_s[r*65 + f0],     geo_s[r*65 + f0 + 1]);
    const u64 g23 = pk2(geo_s[r*65 + f0 + 2], geo_s[r*65 + f0 + 3]);
    u64 a01 = 0, a23 = 0;

    #pragma unroll 8
    for (int d = 0; d < DD; d++) {
        float rpv = rp_s[d*17 + r];                          // 1 phase
        u64 rr = pk2(rpv, rpv);
        double2 fp = *(const double2*)&fp_s[d*68 + f0];      // LDS.128 broadcast
        double2 wz = *(const double2*)&wz_s[4*d];            // {wd,wd},{w2,w2} broadcast
        u64 v01 = add2v(rr, d2u_lo(fp));
        u64 v23 = add2v(rr, d2u_hi(fp));
        v01 = fma2v(g01, d2u_lo(wz), v01);
        v23 = fma2v(g23, d2u_lo(wz), v23);
        float x0, x1, x2, x3;
        upk2(v01, x0, x1);
        upk2(v23, x2, x3);
        x0 = fmaxf(x0, 0.f);
        x1 = fmaxf(x1, 0.f);
        x2 = fmaxf(x2, 0.f);
        x3 = fmaxf(x3, 0.f);
        a01 = fma2v(pk2(x0, x1), d2u_hi(wz), a01);
        a23 = fma2v(pk2(x2, x3), d2u_hi(wz), a23);
    }

    float s0, s1, s2, s3;
    upk2(a01, s0, s1);
    upk2(a23, s2, s3);
    const float b2v = b2[0];
    float e0 = __expf(fmaxf(s0 + b2v, 0.f));   // scores >= 0, small: exact softmax w/o max-sub
    float e1 = __expf(fmaxf(s1 + b2v, 0.f));
    float e2 = __expf(fmaxf(s2 + b2v, 0.f));
    float e3 = __expf(fmaxf(s3 + b2v, 0.f));
    e_s[(f0+0)*17 + r] = e0;
    e_s[(f0+1)*17 + r] = e1;
    e_s[(f0+2)*17 + r] = e2;
    e_s[(f0+3)*17 + r] = e3;
    ps_s[r*16 + fx] = (e0 + e1) + (e2 + e3);

    float* EO = g_escore + (size_t)(b*RR + rbase + r)*FF + fbase;
    *(float4*)&EO[f0] = make_float4(e0, e1, e2, e3);
    __syncthreads();

    if (t < 16) {
        float s = 0.f;
        #pragma unroll
        for (int q = 0; q < 16; q++) s += ps_s[t*16 + q];
        g_sums_part[ftile*(BB*RR) + b*RR + rbase + t] = s;
    }

    // ---- phase B: partial messages, 1r x 8d per thread, packed ----
    const int dg = t >> 4, r2 = t & 15;
    const int d0 = dg*8;
    u64 m01 = 0, m23 = 0, m45 = 0, m67 = 0;

    #pragma unroll 4
    for (int f = 0; f < FT; f++) {
        float ev = e_s[f*17 + r2];                           // 1 phase
        u64 ee = pk2(ev, ev);
        double2 fA = *(const double2*)&fr_s[f*132 + d0];     // LDS.128 broadcast
        double2 fB = *(const double2*)&fr_s[f*132 + d0 + 4];
        m01 = fma2v(ee, d2u_lo(fA), m01);
        m23 = fma2v(ee, d2u_hi(fA), m23);
        m45 = fma2v(ee, d2u_lo(fB), m45);
        m67 = fma2v(ee, d2u_hi(fB), m67);
    }

    float q0,q1,q2,q3,q4,q5,q6,q7;
    upk2(m01, q0, q1);
    upk2(m23, q2, q3);
    upk2(m45, q4, q5);
    upk2(m67, q6, q7);
    float* MO = g_msg_part + (size_t)(ftile*(BB*RR) + b*RR + rbase + r2)*DD;
    *(float4*)&MO[d0]     = make_float4(q0, q1, q2, q3);
    *(float4*)&MO[d0 + 4] = make_float4(q4, q5, q6, q7);
}

// ---------------- kernel 3: normalize + outputs ----------------------------
// grid = 256 (one per (b,r)), 128 threads
__global__ __launch_bounds__(128)
void k3_out(const float* __restrict__ robot,
            const float* __restrict__ Wn,
            const float* __restrict__ bn,
            float* __restrict__ out) {
    __shared__ float comb[2*DD];
    const int br = blockIdx.x;
    const int t  = threadIdx.x;

    float s = 0.f;
    #pragma unroll
    for (int p = 0; p < NFT; p++) s += g_sums_part[p*(BB*RR) + br];
    const float inv = 1.0f / s;

    float mm = 0.f;
    #pragma unroll
    for (int p = 0; p < NFT; p++) mm += g_msg_part[(size_t)(p*(BB*RR) + br)*DD + t];
    comb[DD + t] = mm * inv;
    comb[t]      = robot[(size_t)br*DD + t];

    const float* E  = g_escore + (size_t)br*FF;
    float*       ew = out + (size_t)BB*RR*DD + (size_t)br*FF;
    #pragma unroll
    for (int k = 0; k < FF/DD; k++) ew[k*DD + t] = E[k*DD + t] * inv;
    __syncthreads();

    float acc = bn[t];
    #pragma unroll 8
    for (int k = 0; k < 2*DD; k++) acc = fmaf(comb[k], Wn[k*DD + t], acc);
    out[(size_t)br*DD + t] = fmaxf(acc, 0.f);
}

// ---------------- launch ----------------------------------------------------
extern "C" void kernel_launch(void* const* d_in, const int* in_sizes, int n_in,
                              void* d_out, int out_size) {
    const float* robot    = (const float*)d_in[0];
    const float* frontier = (const float*)d_in[1];
    const float* geo      = (const float*)d_in[2];
    const float* W1       = (const float*)d_in[3];
    const float* b1       = (const float*)d_in[4];
    const float* W2       = (const float*)d_in[5];
    const float* b2       = (const float*)d_in[6];
    const float* Wn       = (const float*)d_in[7];
    const float* bn       = (const float*)d_in[8];
    float* out = (float*)d_out;

    cudaFuncSetAttribute(k1_proj, cudaFuncAttributeMaxDynamicSharedMemorySize, K1_SMEM);
    cudaFuncSetAttribute(k2_main, cudaFuncAttributeMaxDynamicSharedMemorySize, K2_SMEM);

    k1_proj<<<545, 256, K1_SMEM>>>(robot, frontier, W1, b1);
    k2_main<<<256, 256, K2_SMEM>>>(frontier, geo, W2, b2);
    k3_out<<<256, 128>>>(robot, Wn, bn, out);
}